// round 13
// baseline (speedup 1.0000x reference)
#include <cuda_runtime.h>
#include <cuda_bf16.h>
#include <cuda_fp16.h>
#include <cstdint>
#include <math.h>

#define B_ 8
#define C_ 256
#define HID_ 64
#define H_ 64
#define W_ 64
#define N_ 4096
#define KTOT 2304          // 9 taps * 256 ci
#define NKCH 36            // KTOT / 64

// ---------------- device scratch ----------------
__device__ __align__(256) __nv_bfloat16 g_q_hi[(size_t)B_ * N_ * HID_];
__device__ __align__(256) __nv_bfloat16 g_q_lo[(size_t)B_ * N_ * HID_];
__device__ __align__(256) __nv_bfloat16 g_k_hi[(size_t)B_ * N_ * HID_];
__device__ __align__(256) __nv_bfloat16 g_k_lo[(size_t)B_ * N_ * HID_];
__device__ __align__(256) __half        g_v_h[(size_t)B_ * C_ * N_];    // fp16 V
// x transposed+split: [b][n][ci]
__device__ __align__(256) __nv_bfloat16 g_xt_hi[(size_t)B_ * N_ * C_];
__device__ __align__(256) __nv_bfloat16 g_xt_lo[(size_t)B_ * N_ * C_];
// stacked weights [co 0..383][tap*256+ci]  (0-63 q, 64-127 k, 128-383 v)
__device__ __align__(256) __nv_bfloat16 g_w_hi[384 * KTOT], g_w_lo[384 * KTOT];

// ---------------- PTX helpers (sm_80-compatible only) ----------------
__device__ __forceinline__ uint32_t smem_u32(const void* p) {
    uint32_t a;
    asm("{ .reg .u64 t; cvta.to.shared.u64 t, %1; cvt.u32.u64 %0, t; }" : "=r"(a) : "l"(p));
    return a;
}
#define SWZ(x) ((uint32_t)(x) ^ ((((uint32_t)(x)) >> 3) & 0x70u))

__device__ __forceinline__ void cpa16(uint32_t dst, const void* src) {
    asm volatile("cp.async.cg.shared.global [%0], [%1], 16;" :: "r"(dst), "l"(src));
}
__device__ __forceinline__ void cpa16z(uint32_t dst, const void* src, uint32_t sz) {
    asm volatile("cp.async.cg.shared.global [%0], [%1], 16, %2;"
                 :: "r"(dst), "l"(src), "r"(sz));
}
#define CP_COMMIT() asm volatile("cp.async.commit_group;")
#define CP_WAIT(n)  asm volatile("cp.async.wait_group %0;" :: "n"(n))

__device__ __forceinline__ void ldm_x4(uint32_t a, uint32_t* r) {
    asm volatile("ldmatrix.sync.aligned.m8n8.x4.shared.b16 {%0,%1,%2,%3}, [%4];"
        : "=r"(r[0]), "=r"(r[1]), "=r"(r[2]), "=r"(r[3]) : "r"(a));
}
__device__ __forceinline__ void mma_bf16(float* d, const uint32_t* a, const uint32_t* b) {
    asm volatile("mma.sync.aligned.m16n8k16.row.col.f32.bf16.bf16.f32 "
        "{%0,%1,%2,%3}, {%4,%5,%6,%7}, {%8,%9}, {%0,%1,%2,%3};"
        : "+f"(d[0]), "+f"(d[1]), "+f"(d[2]), "+f"(d[3])
        : "r"(a[0]), "r"(a[1]), "r"(a[2]), "r"(a[3]), "r"(b[0]), "r"(b[1]));
}
__device__ __forceinline__ void mma_f16(float* d, const uint32_t* a, const uint32_t* b) {
    asm volatile("mma.sync.aligned.m16n8k16.row.col.f32.f16.f16.f32 "
        "{%0,%1,%2,%3}, {%4,%5,%6,%7}, {%8,%9}, {%0,%1,%2,%3};"
        : "+f"(d[0]), "+f"(d[1]), "+f"(d[2]), "+f"(d[3])
        : "r"(a[0]), "r"(a[1]), "r"(a[2]), "r"(a[3]), "r"(b[0]), "r"(b[1]));
}
__device__ __forceinline__ uint32_t pack_bf2(float a, float b) {
    __nv_bfloat162 t = __floats2bfloat162_rn(a, b);
    return *(uint32_t*)&t;
}

// ---------------------------------------------------------------------------
// Prep 1: x [b][ci][n] fp32 -> g_xt_hi/lo [b][n][ci] bf16. grid(64,4,8), 256 thr
// ---------------------------------------------------------------------------
__global__ __launch_bounds__(256) void xsplit_kernel(const float* __restrict__ x)
{
    __shared__ float st[64][65];
    const int b = blockIdx.z, ci0 = blockIdx.y * 64, n0 = blockIdx.x * 64;
    const int tid = threadIdx.x, L = tid & 31, w = tid >> 5;
#pragma unroll
    for (int i = 0; i < 4; i++) {
        int j = i * 256 + tid;
        int ci = j >> 4, c4 = (j & 15) * 4;
        float4 v = *(const float4*)(x + ((size_t)b * C_ + ci0 + ci) * N_ + n0 + c4);
        st[ci][c4] = v.x; st[ci][c4 + 1] = v.y; st[ci][c4 + 2] = v.z; st[ci][c4 + 3] = v.w;
    }
    __syncthreads();
#pragma unroll
    for (int i = 0; i < 8; i++) {
        int n = w * 8 + i;
        float v0 = st[2 * L][n], v1 = st[2 * L + 1][n];
        __nv_bfloat16 h0 = __float2bfloat16(v0), h1 = __float2bfloat16(v1);
        float l0 = v0 - __bfloat162float(h0), l1 = v1 - __bfloat162float(h1);
        size_t gb = ((size_t)b * N_ + n0 + n) * C_ + ci0;
        __nv_bfloat162 hh; hh.x = h0; hh.y = h1;
        *(uint32_t*)((char*)g_xt_hi + gb * 2 + L * 4) = *(uint32_t*)&hh;
        *(uint32_t*)((char*)g_xt_lo + gb * 2 + L * 4) = pack_bf2(l0, l1);
    }
}

// ---------------------------------------------------------------------------
// Prep 2: stack+repack weights: W[co][ci][3][3] -> g_w[co][tap*256+ci] hi/lo
// ---------------------------------------------------------------------------
__global__ __launch_bounds__(256) void wsplit_kernel(
    const float* __restrict__ Wq, const float* __restrict__ Wk,
    const float* __restrict__ Wv)
{
    int t = blockIdx.x * 256 + threadIdx.x;   // 0..98303
    int co = t >> 8, ci = t & 255;
    const float* src;
    int lc;
    if (co < 64)       { src = Wq; lc = co; }
    else if (co < 128) { src = Wk; lc = co - 64; }
    else               { src = Wv; lc = co - 128; }
#pragma unroll
    for (int kk = 0; kk < 9; kk++) {
        float v = src[((size_t)lc * 256 + ci) * 9 + kk];
        __nv_bfloat16 h = __float2bfloat16(v);
        size_t o = (size_t)co * KTOT + kk * 256 + ci;
        g_w_hi[o] = h;
        g_w_lo[o] = __float2bfloat16(v - __bfloat162float(h));
    }
}

// ---------------------------------------------------------------------------
// QKV GEMM, implicit im2col (R11-proven). V epilogue now writes fp16 1-plane.
// ---------------------------------------------------------------------------
#define GM_B_OFF 98304
#define GM_TOT   196608

__device__ __forceinline__ void gemm_stage(uint32_t sb, int co0, int b, int ntile,
                                           int kc, int buf, int tid) {
    const int tap = kc >> 2, cic = kc & 3;
    const int dy = tap / 3 - 1, dx = tap % 3 - 1;
#pragma unroll
    for (int i = 0; i < 4; i++) {       // A: weights [128 co][64 k]
        int idx = tid + i * 512;
        int plane = idx >> 10;
        int rem = idx & 1023;
        int row = rem >> 3, c16 = rem & 7;
        const char* src = (plane ? (const char*)g_w_lo : (const char*)g_w_hi) +
                          (((size_t)(co0 + row)) * KTOT + kc * 64 + c16 * 8) * 2;
        cpa16(sb + buf * 32768 + plane * 16384 + SWZ(row * 128 + c16 * 16), src);
    }
#pragma unroll
    for (int i = 0; i < 4; i++) {       // B: shifted xt rows, zero-fill halo
        int idx = tid + i * 512;
        int plane = idx >> 10;
        int rem = idx & 1023;
        int row = rem >> 3, c16 = rem & 7;
        int n = ntile * 128 + row;
        int iy = (n >> 6) + dy;
        int ix = (n & 63) + dx;
        bool ok = (iy >= 0) && (iy < H_) && (ix >= 0) && (ix < W_);
        size_t so = ((size_t)b * N_ + (size_t)(ok ? (iy * 64 + ix) : 0)) * C_ +
                    cic * 64 + c16 * 8;
        const char* src = (plane ? (const char*)g_xt_lo : (const char*)g_xt_hi) + so * 2;
        cpa16z(sb + GM_B_OFF + buf * 32768 + plane * 16384 + SWZ(row * 128 + c16 * 16),
               src, ok ? 16u : 0u);
    }
}

__global__ void __launch_bounds__(512, 1) gemm_qkv_kernel(
    const float* __restrict__ bq, const float* __restrict__ bk,
    const float* __restrict__ bv)
{
    extern __shared__ char smem[];
    uint32_t sb = smem_u32(smem);
    const int tid = threadIdx.x, L = tid & 31, w = tid >> 5;
    const int mw = w & 3, nw = w >> 2;
    const int cot = blockIdx.x, ntile = blockIdx.y, b = blockIdx.z;
    const int co0 = cot * 128;

    uint32_t RAm[2], sAm[2];
#pragma unroll
    for (int m = 0; m < 2; m++) {
        uint32_t row = (uint32_t)(mw * 32 + m * 16 + (L & 15));
        RAm[m] = row * 128;
        sAm[m] = (row & 7) << 4;
    }
    const uint32_t colA = (L & 16) ? 16u : 0u;
    uint32_t RB[2], sB[2];
#pragma unroll
    for (int j = 0; j < 2; j++) {
        uint32_t row = (uint32_t)((nw * 4 + j * 2 + (L >> 4)) * 8 + (L & 7));
        RB[j] = row * 128;
        sB[j] = (row & 7) << 4;
    }
    const uint32_t colB = (uint32_t)(L & 8) * 2;

    float d[8][4];
#pragma unroll
    for (int f = 0; f < 8; f++)
#pragma unroll
        for (int i = 0; i < 4; i++) d[f][i] = 0.f;

    gemm_stage(sb, co0, b, ntile, 0, 0, tid);
    CP_COMMIT();
    gemm_stage(sb, co0, b, ntile, 1, 1, tid);
    CP_COMMIT();

#pragma unroll 1
    for (int kc = 0; kc < NKCH; kc++) {
        const int buf = kc % 3;
        if (kc == NKCH - 1) { CP_WAIT(0); } else { CP_WAIT(1); }
        __syncthreads();
        if (kc < NKCH - 2) {
            gemm_stage(sb, co0, b, ntile, kc + 2, (kc + 2) % 3, tid);
            CP_COMMIT();
        }

        const uint32_t Ab = sb + buf * 32768;
        const uint32_t Bb = sb + GM_B_OFF + buf * 32768;
#pragma unroll
        for (int pass = 0; pass < 3; pass++) {
            const uint32_t Ap = Ab + ((pass == 2) ? 16384u : 0u);
            const uint32_t Bp = Bb + ((pass == 1) ? 16384u : 0u);
#pragma unroll
            for (int kk = 0; kk < 4; kk++) {
                const uint32_t kca = (uint32_t)(kk * 32) + colA;
                const uint32_t kcb = (uint32_t)(kk * 32) + colB;
                uint32_t a0[4], a1[4];
                ldm_x4(Ap + RAm[0] + (kca ^ sAm[0]), a0);
                ldm_x4(Ap + RAm[1] + (kca ^ sAm[1]), a1);
#pragma unroll
                for (int j = 0; j < 2; j++) {
                    uint32_t bb[4];
                    ldm_x4(Bp + RB[j] + (kcb ^ sB[j]), bb);
                    mma_bf16(d[2 * j],         a0, bb);
                    mma_bf16(d[2 * j + 1],     a0, bb + 2);
                    mma_bf16(d[4 + 2 * j],     a1, bb);
                    mma_bf16(d[4 + 2 * j + 1], a1, bb + 2);
                }
            }
        }
    }

    // ---- epilogue
    __syncthreads();
    float* sD = (float*)smem;
#pragma unroll
    for (int m = 0; m < 2; m++)
#pragma unroll
        for (int jn = 0; jn < 4; jn++) {
            int f = m * 4 + jn;
            int r0 = mw * 32 + m * 16 + (L >> 2);
            int n0 = nw * 32 + jn * 8 + 2 * (L & 3);
            sD[r0 * 130 + n0]           = d[f][0];
            sD[r0 * 130 + n0 + 1]       = d[f][1];
            sD[(r0 + 8) * 130 + n0]     = d[f][2];
            sD[(r0 + 8) * 130 + n0 + 1] = d[f][3];
        }
    __syncthreads();

    const size_t bn0 = (size_t)b * N_ + (size_t)ntile * 128;
    if (cot == 0) {
#pragma unroll 1
        for (int i = 0; i < 8; i++) {
            int idx = tid + i * 512;
            int n = idx >> 5, cp = idx & 31;
            {
                float v0 = sD[(2 * cp) * 130 + n]     + bq[2 * cp];
                float v1 = sD[(2 * cp + 1) * 130 + n] + bq[2 * cp + 1];
                __nv_bfloat16 h0 = __float2bfloat16(v0), h1 = __float2bfloat16(v1);
                __nv_bfloat162 hh; hh.x = h0; hh.y = h1;
                size_t off = ((bn0 + n) * HID_ + 2 * cp) * 2;
                *(uint32_t*)((char*)g_q_hi + off) = *(uint32_t*)&hh;
                *(uint32_t*)((char*)g_q_lo + off) =
                    pack_bf2(v0 - __bfloat162float(h0), v1 - __bfloat162float(h1));
            }
            {
                float v0 = sD[(64 + 2 * cp) * 130 + n]     + bk[2 * cp];
                float v1 = sD[(64 + 2 * cp + 1) * 130 + n] + bk[2 * cp + 1];
                __nv_bfloat16 h0 = __float2bfloat16(v0), h1 = __float2bfloat16(v1);
                __nv_bfloat162 hh; hh.x = h0; hh.y = h1;
                size_t off = ((bn0 + n) * HID_ + 2 * cp) * 2;
                *(uint32_t*)((char*)g_k_hi + off) = *(uint32_t*)&hh;
                *(uint32_t*)((char*)g_k_lo + off) =
                    pack_bf2(v0 - __bfloat162float(h0), v1 - __bfloat162float(h1));
            }
        }
    } else {
        const int cv0 = (cot - 1) * 128;
        const size_t n0g = (size_t)ntile * 128;
#pragma unroll 1
        for (int i = 0; i < 16; i++) {
            int idx = tid + i * 512;
            int co = idx >> 6, np = idx & 63;
            float bb = bv[cv0 + co];
            float v0 = sD[co * 130 + 2 * np]     + bb;
            float v1 = sD[co * 130 + 2 * np + 1] + bb;
            __half2 hh = __floats2half2_rn(v0, v1);
            size_t off = (((size_t)b * C_ + cv0 + co) * N_ + n0g + 2 * np) * 2;
            *(uint32_t*)((char*)g_v_h + off) = *(uint32_t*)&hh;
        }
    }
}

// ---------------------------------------------------------------------------
// Flash attention: S on bf16 hi/lo (3-pass), ONLINE softmax, P+V fp16 1-plane.
// ---------------------------------------------------------------------------
#define SM_Q_HI 0
#define SM_Q_LO 16384
#define SM_P    32768
#define SM_RS   49152
#define SM_MX   50176
#define SM_K    51200                 // + buf*16384 ; hi +0, lo +8192
#define SM_V    83968                 // + buf*32768 (fp16 single plane)
#define SM_TOT  215040                // SM_V + 131072 (epilogue staging)

__device__ __forceinline__ void load_qtile(uint32_t sb, int b, int m0, int tid) {
    const char* qh = (const char*)g_q_hi + ((size_t)b * N_ + m0) * HID_ * 2;
    const char* ql = (const char*)g_q_lo + ((size_t)b * N_ + m0) * HID_ * 2;
#pragma unroll
    for (int i = 0; i < 2; i++) {
        int idx = tid + i * 512;
        int row = idx >> 3, c = (idx & 7) * 16;
        uint32_t off = SWZ(row * 128 + c);
        cpa16(sb + SM_Q_HI + off, qh + row * 128 + c);
        cpa16(sb + SM_Q_LO + off, ql + row * 128 + c);
    }
}

__device__ __forceinline__ void load_kv(uint32_t sb, int b, int nt, int tid) {
    const int buf = nt & 1;
    const char* kh = (const char*)g_k_hi + ((size_t)b * N_ + (size_t)nt * 64) * HID_ * 2;
    const char* kl = (const char*)g_k_lo + ((size_t)b * N_ + (size_t)nt * 64) * HID_ * 2;
    {
        int row = tid >> 3, c = (tid & 7) * 16;
        uint32_t off = SWZ(row * 128 + c);
        cpa16(sb + SM_K + buf * 16384 + off, kh + row * 128 + c);
        cpa16(sb + SM_K + buf * 16384 + 8192 + off, kl + row * 128 + c);
    }
    const char* vh = (const char*)g_v_h + ((size_t)b * C_ * N_ + (size_t)nt * 64) * 2;
#pragma unroll
    for (int i = 0; i < 4; i++) {
        int idx = tid + i * 512;              // 0..2047 chunks
        int row = idx >> 3, c = (idx & 7) * 16;
        cpa16(sb + SM_V + buf * 32768 + SWZ(row * 128 + c),
              vh + (size_t)row * (N_ * 2) + c);
    }
}

__global__ void __launch_bounds__(512, 1) flash_mma_kernel(
    const float* __restrict__ x, float* __restrict__ out)
{
    extern __shared__ char smem[];
    uint32_t sb = smem_u32(smem);
    const int tid = threadIdx.x;
    const int L   = tid & 31;
    const int w   = tid >> 5;
    const int rb  = w & 7;
    const int ch  = w >> 3;
    const int b   = blockIdx.y;
    const int m0  = blockIdx.x * 128;

    load_qtile(sb, b, m0, tid);
    load_kv(sb, b, 0, tid);
    CP_COMMIT();
    load_kv(sb, b, 1, tid);
    CP_COMMIT();

    const uint32_t RA   = (uint32_t)(rb * 16 + (L & 15)) * 128;
    const uint32_t sA   = (RA >> 3) & 0x70;
    const uint32_t colA = (L & 16) ? 16u : 0u;
    uint32_t RBs[2], sBs[2];
#pragma unroll
    for (int nnb = 0; nnb < 2; nnb++) {
        uint32_t row = (uint32_t)((ch * 4 + nnb * 2 + (L >> 4)) * 8 + (L & 7));
        RBs[nnb] = row * 128;
        sBs[nnb] = (RBs[nnb] >> 3) & 0x70;
    }
    const uint32_t colB = (uint32_t)(L & 8) * 2;
    const uint32_t colV = (uint32_t)((L & 8) * 2 + (L & 16) * 2);
    const uint32_t RP0  = (uint32_t)(rb * 16 + (L >> 2)) * 128;
    const uint32_t sP0  = (RP0 >> 3) & 0x70;
    const uint32_t RP1  = RP0 + 8 * 128;
    const uint32_t sP1  = (RP1 >> 3) & 0x70;
    const int rown = rb * 16 + (L >> 2);
    float* sRS = (float*)(smem + SM_RS);
    float* sMX = (float*)(smem + SM_MX);

    float O[16][4];
#pragma unroll
    for (int cc = 0; cc < 16; cc++)
#pragma unroll
        for (int i = 0; i < 4; i++) O[cc][i] = 0.f;
    float l0 = 0.f, l1 = 0.f;
    float mr0 = -INFINITY, mr1 = -INFINITY;

    for (int nt = 0; nt < 64; nt++) {
        const int buf = nt & 1;
        if (nt == 63) { CP_WAIT(0); } else { CP_WAIT(1); }
        __syncthreads();

        // ---- S = Qhi*Khi + Qhi*Klo + Qlo*Khi (bf16, fp32 accum)
        float d[4][4];
#pragma unroll
        for (int nn = 0; nn < 4; nn++)
#pragma unroll
            for (int i = 0; i < 4; i++) d[nn][i] = 0.f;

        const uint32_t kb0 = sb + SM_K + buf * 16384;
#pragma unroll 1
        for (int pass = 0; pass < 3; pass++) {
            uint32_t qbase = (pass == 2) ? (sb + SM_Q_LO) : (sb + SM_Q_HI);
            uint32_t kbase = kb0 + ((pass == 1) ? 8192u : 0u);
#pragma unroll
            for (int kk = 0; kk < 4; kk++) {
                uint32_t a[4];
                ldm_x4(qbase + RA + ((kk * 32 + colA) ^ sA), a);
#pragma unroll
                for (int nnb = 0; nnb < 2; nnb++) {
                    uint32_t bb[4];
                    ldm_x4(kbase + RBs[nnb] + (((uint32_t)(kk * 32) + colB) ^ sBs[nnb]), bb);
                    mma_bf16(d[nnb * 2],     a, bb);
                    mma_bf16(d[nnb * 2 + 1], a, bb + 2);
                }
            }
        }

        // ---- online row max (4-lane shfl + cross-warp exchange)
        float mx0 = fmaxf(fmaxf(d[0][0], d[0][1]), fmaxf(d[1][0], d[1][1]));
        mx0 = fmaxf(mx0, fmaxf(fmaxf(d[2][0], d[2][1]), fmaxf(d[3][0], d[3][1])));
        float mx1 = fmaxf(fmaxf(d[0][2], d[0][3]), fmaxf(d[1][2], d[1][3]));
        mx1 = fmaxf(mx1, fmaxf(fmaxf(d[2][2], d[2][3]), fmaxf(d[3][2], d[3][3])));
        mx0 = fmaxf(mx0, __shfl_xor_sync(~0u, mx0, 1));
        mx0 = fmaxf(mx0, __shfl_xor_sync(~0u, mx0, 2));
        mx1 = fmaxf(mx1, __shfl_xor_sync(~0u, mx1, 1));
        mx1 = fmaxf(mx1, __shfl_xor_sync(~0u, mx1, 2));
        if ((L & 3) == 0) {
            sMX[ch * 128 + rown]     = mx0;
            sMX[ch * 128 + rown + 8] = mx1;
        }
        __syncthreads();
        mx0 = fmaxf(mx0, sMX[(ch ^ 1) * 128 + rown]);
        mx1 = fmaxf(mx1, sMX[(ch ^ 1) * 128 + rown + 8]);
        const float mn0 = fmaxf(mr0, mx0), mn1 = fmaxf(mr1, mx1);
        const float a0 = __expf(mr0 - mn0), a1 = __expf(mr1 - mn1);
        mr0 = mn0; mr1 = mn1;

        // ---- p = exp(s - rowmax) -> fp16; l accumulates the ROUNDED p
        float ps0 = 0.f, ps1 = 0.f;
#pragma unroll
        for (int nn = 0; nn < 4; nn++) {
            float e00 = __expf(d[nn][0] - mn0), e01 = __expf(d[nn][1] - mn0);
            float e10 = __expf(d[nn][2] - mn1), e11 = __expf(d[nn][3] - mn1);
            __half2 p0 = __floats2half2_rn(e00, e01);
            __half2 p1 = __floats2half2_rn(e10, e11);
            float2 f0 = __half22float2(p0);
            float2 f1 = __half22float2(p1);
            ps0 += f0.x + f0.y; ps1 += f1.x + f1.y;
            uint32_t cbyte = (uint32_t)((ch * 32 + nn * 8 + 2 * (L & 3)) * 2);
            *(uint32_t*)(smem + SM_P + RP0 + (cbyte ^ sP0)) = *(uint32_t*)&p0;
            *(uint32_t*)(smem + SM_P + RP1 + (cbyte ^ sP1)) = *(uint32_t*)&p1;
        }
        ps0 += __shfl_xor_sync(~0u, ps0, 1);
        ps0 += __shfl_xor_sync(~0u, ps0, 2);
        ps1 += __shfl_xor_sync(~0u, ps1, 1);
        ps1 += __shfl_xor_sync(~0u, ps1, 2);
        if ((L & 3) == 0) {
            sRS[ch * 128 + rown]     = ps0;
            sRS[ch * 128 + rown + 8] = ps1;
        }
        __syncthreads();
        l0 = l0 * a0 + ps0 + sRS[(ch ^ 1) * 128 + rown];
        l1 = l1 * a1 + ps1 + sRS[(ch ^ 1) * 128 + rown + 8];

        // ---- rescale O, then O += P * V (fp16)
#pragma unroll
        for (int cc = 0; cc < 16; cc++) {
            O[cc][0] *= a0; O[cc][1] *= a0; O[cc][2] *= a1; O[cc][3] *= a1;
        }

        uint32_t pa[4][4];
#pragma unroll
        for (int kk = 0; kk < 4; kk++)
            ldm_x4(sb + SM_P + RA + ((kk * 32 + colA) ^ sA), pa[kk]);

        const uint32_t vb0 = sb + SM_V + buf * 32768;
#pragma unroll
        for (int cc = 0; cc < 16; cc++) {
            uint32_t row = (uint32_t)(ch * 128 + cc * 8 + (L & 7));
            uint32_t RB = row * 128, sB = (row & 7) << 4;
            uint32_t vb = vb0 + RB;
            uint32_t b01[4], b23[4];
            ldm_x4(vb + (colV ^ sB), b01);
            ldm_x4(vb + ((64 + colV) ^ sB), b23);
            mma_f16(O[cc], pa[0], b01); mma_f16(O[cc], pa[1], b01 + 2);
            mma_f16(O[cc], pa[2], b23); mma_f16(O[cc], pa[3], b23 + 2);
        }
        __syncthreads();
        if (nt < 62) { load_kv(sb, b, nt + 2, tid); CP_COMMIT(); }
    }

    const float inv0 = 1.f / l0, inv1 = 1.f / l1;
    float* sO = (float*)(smem + SM_V + ch * 65536);
    const int gg = rb * 16 + (L >> 2), tt = L & 3;
#pragma unroll
    for (int cc = 0; cc < 16; cc++) {
        int c0 = cc * 8 + 2 * tt;
        sO[c0 * 128 + gg]           = O[cc][0] * inv0;
        sO[(c0 + 1) * 128 + gg]     = O[cc][1] * inv0;
        sO[c0 * 128 + gg + 8]       = O[cc][2] * inv1;
        sO[(c0 + 1) * 128 + gg + 8] = O[cc][3] * inv1;
    }
    __syncthreads();

    const float* xb = x   + (size_t)b * C_ * N_ + m0;
    float*       ob = out + (size_t)b * C_ * N_ + m0;
#pragma unroll 1
    for (int i = 0; i < 16; i++) {
        int idx = tid + i * 512;
        int c = idx >> 5, m4 = (idx & 31) * 4;
        float4 vo = *(float4*)(smem + SM_V + (size_t)(c >> 7) * 65536 +
                               (size_t)(c & 127) * 512 + (size_t)m4 * 4);
        float4 vx = *(const float4*)(xb + (size_t)c * N_ + m4);
        vo.x += vx.x; vo.y += vx.y; vo.z += vx.z; vo.w += vx.w;
        *(float4*)(ob + (size_t)c * N_ + m4) = vo;
    }
}

// ---------------------------------------------------------------------------
extern "C" void kernel_launch(void* const* d_in, const int* in_sizes, int n_in,
                              void* d_out, int out_size)
{
    const float* x  = (const float*)d_in[0];
    const float* Wq = (const float*)d_in[1];
    const float* bq = (const float*)d_in[2];
    const float* Wk = (const float*)d_in[3];
    const float* bk = (const float*)d_in[4];
    const float* Wv = (const float*)d_in[5];
    const float* bv = (const float*)d_in[6];
    float* out = (float*)d_out;

    xsplit_kernel<<<dim3(64, 4, 8), 256>>>(x);
    wsplit_kernel<<<384, 256>>>(Wq, Wk, Wv);

    cudaFuncSetAttribute(gemm_qkv_kernel,
                         cudaFuncAttributeMaxDynamicSharedMemorySize, GM_TOT);
    gemm_qkv_kernel<<<dim3(3, 32, 8), 512, GM_TOT>>>(bq, bk, bv);

    cudaFuncSetAttribute(flash_mma_kernel,
                         cudaFuncAttributeMaxDynamicSharedMemorySize, SM_TOT);
    flash_mma_kernel<<<dim3(32, 8), 512, SM_TOT>>>(x, out);
}

// round 14
// speedup vs baseline: 1.1501x; 1.1501x over previous
#include <cuda_runtime.h>
#include <cuda_bf16.h>
#include <cuda_fp16.h>
#include <cstdint>
#include <math.h>

#define B_ 8
#define C_ 256
#define HID_ 64
#define H_ 64
#define W_ 64
#define N_ 4096
#define KTOT 2304          // 9 taps * 256 ci
#define NKCH 36            // KTOT / 64

// ---------------- device scratch ----------------
__device__ __align__(256) __half        g_q_h[(size_t)B_ * N_ * HID_];  // fp16 Q
__device__ __align__(256) __half        g_k_h[(size_t)B_ * N_ * HID_];  // fp16 K
__device__ __align__(256) __half        g_v_h[(size_t)B_ * C_ * N_];    // fp16 V
// x transposed+split: [b][n][ci]
__device__ __align__(256) __nv_bfloat16 g_xt_hi[(size_t)B_ * N_ * C_];
__device__ __align__(256) __nv_bfloat16 g_xt_lo[(size_t)B_ * N_ * C_];
// stacked weights [co 0..383][tap*256+ci]  (0-63 q, 64-127 k, 128-383 v)
__device__ __align__(256) __nv_bfloat16 g_w_hi[384 * KTOT], g_w_lo[384 * KTOT];

// ---------------- PTX helpers (sm_80-compatible only) ----------------
__device__ __forceinline__ uint32_t smem_u32(const void* p) {
    uint32_t a;
    asm("{ .reg .u64 t; cvta.to.shared.u64 t, %1; cvt.u32.u64 %0, t; }" : "=r"(a) : "l"(p));
    return a;
}
#define SWZ(x) ((uint32_t)(x) ^ ((((uint32_t)(x)) >> 3) & 0x70u))

__device__ __forceinline__ void cpa16(uint32_t dst, const void* src) {
    asm volatile("cp.async.cg.shared.global [%0], [%1], 16;" :: "r"(dst), "l"(src));
}
__device__ __forceinline__ void cpa16z(uint32_t dst, const void* src, uint32_t sz) {
    asm volatile("cp.async.cg.shared.global [%0], [%1], 16, %2;"
                 :: "r"(dst), "l"(src), "r"(sz));
}
#define CP_COMMIT() asm volatile("cp.async.commit_group;")
#define CP_WAIT(n)  asm volatile("cp.async.wait_group %0;" :: "n"(n))

__device__ __forceinline__ void ldm_x4(uint32_t a, uint32_t* r) {
    asm volatile("ldmatrix.sync.aligned.m8n8.x4.shared.b16 {%0,%1,%2,%3}, [%4];"
        : "=r"(r[0]), "=r"(r[1]), "=r"(r[2]), "=r"(r[3]) : "r"(a));
}
__device__ __forceinline__ void mma_bf16(float* d, const uint32_t* a, const uint32_t* b) {
    asm volatile("mma.sync.aligned.m16n8k16.row.col.f32.bf16.bf16.f32 "
        "{%0,%1,%2,%3}, {%4,%5,%6,%7}, {%8,%9}, {%0,%1,%2,%3};"
        : "+f"(d[0]), "+f"(d[1]), "+f"(d[2]), "+f"(d[3])
        : "r"(a[0]), "r"(a[1]), "r"(a[2]), "r"(a[3]), "r"(b[0]), "r"(b[1]));
}
__device__ __forceinline__ void mma_f16(float* d, const uint32_t* a, const uint32_t* b) {
    asm volatile("mma.sync.aligned.m16n8k16.row.col.f32.f16.f16.f32 "
        "{%0,%1,%2,%3}, {%4,%5,%6,%7}, {%8,%9}, {%0,%1,%2,%3};"
        : "+f"(d[0]), "+f"(d[1]), "+f"(d[2]), "+f"(d[3])
        : "r"(a[0]), "r"(a[1]), "r"(a[2]), "r"(a[3]), "r"(b[0]), "r"(b[1]));
}
__device__ __forceinline__ uint32_t pack_bf2(float a, float b) {
    __nv_bfloat162 t = __floats2bfloat162_rn(a, b);
    return *(uint32_t*)&t;
}

// ---------------------------------------------------------------------------
// Prep 1: x [b][ci][n] fp32 -> g_xt_hi/lo [b][n][ci] bf16. grid(64,4,8), 256 thr
// ---------------------------------------------------------------------------
__global__ __launch_bounds__(256) void xsplit_kernel(const float* __restrict__ x)
{
    __shared__ float st[64][65];
    const int b = blockIdx.z, ci0 = blockIdx.y * 64, n0 = blockIdx.x * 64;
    const int tid = threadIdx.x, L = tid & 31, w = tid >> 5;
#pragma unroll
    for (int i = 0; i < 4; i++) {
        int j = i * 256 + tid;
        int ci = j >> 4, c4 = (j & 15) * 4;
        float4 v = *(const float4*)(x + ((size_t)b * C_ + ci0 + ci) * N_ + n0 + c4);
        st[ci][c4] = v.x; st[ci][c4 + 1] = v.y; st[ci][c4 + 2] = v.z; st[ci][c4 + 3] = v.w;
    }
    __syncthreads();
#pragma unroll
    for (int i = 0; i < 8; i++) {
        int n = w * 8 + i;
        float v0 = st[2 * L][n], v1 = st[2 * L + 1][n];
        __nv_bfloat16 h0 = __float2bfloat16(v0), h1 = __float2bfloat16(v1);
        float l0 = v0 - __bfloat162float(h0), l1 = v1 - __bfloat162float(h1);
        size_t gb = ((size_t)b * N_ + n0 + n) * C_ + ci0;
        __nv_bfloat162 hh; hh.x = h0; hh.y = h1;
        *(uint32_t*)((char*)g_xt_hi + gb * 2 + L * 4) = *(uint32_t*)&hh;
        *(uint32_t*)((char*)g_xt_lo + gb * 2 + L * 4) = pack_bf2(l0, l1);
    }
}

// ---------------------------------------------------------------------------
// Prep 2: stack+repack weights: W[co][ci][3][3] -> g_w[co][tap*256+ci] hi/lo
// ---------------------------------------------------------------------------
__global__ __launch_bounds__(256) void wsplit_kernel(
    const float* __restrict__ Wq, const float* __restrict__ Wk,
    const float* __restrict__ Wv)
{
    int t = blockIdx.x * 256 + threadIdx.x;   // 0..98303
    int co = t >> 8, ci = t & 255;
    const float* src;
    int lc;
    if (co < 64)       { src = Wq; lc = co; }
    else if (co < 128) { src = Wk; lc = co - 64; }
    else               { src = Wv; lc = co - 128; }
#pragma unroll
    for (int kk = 0; kk < 9; kk++) {
        float v = src[((size_t)lc * 256 + ci) * 9 + kk];
        __nv_bfloat16 h = __float2bfloat16(v);
        size_t o = (size_t)co * KTOT + kk * 256 + ci;
        g_w_hi[o] = h;
        g_w_lo[o] = __float2bfloat16(v - __bfloat162float(h));
    }
}

// ---------------------------------------------------------------------------
// QKV GEMM, implicit im2col (R11-proven mainloop). Q/K epilogue -> fp16 plane.
// ---------------------------------------------------------------------------
#define GM_B_OFF 98304
#define GM_TOT   196608

__device__ __forceinline__ void gemm_stage(uint32_t sb, int co0, int b, int ntile,
                                           int kc, int buf, int tid) {
    const int tap = kc >> 2, cic = kc & 3;
    const int dy = tap / 3 - 1, dx = tap % 3 - 1;
#pragma unroll
    for (int i = 0; i < 4; i++) {       // A: weights [128 co][64 k]
        int idx = tid + i * 512;
        int plane = idx >> 10;
        int rem = idx & 1023;
        int row = rem >> 3, c16 = rem & 7;
        const char* src = (plane ? (const char*)g_w_lo : (const char*)g_w_hi) +
                          (((size_t)(co0 + row)) * KTOT + kc * 64 + c16 * 8) * 2;
        cpa16(sb + buf * 32768 + plane * 16384 + SWZ(row * 128 + c16 * 16), src);
    }
#pragma unroll
    for (int i = 0; i < 4; i++) {       // B: shifted xt rows, zero-fill halo
        int idx = tid + i * 512;
        int plane = idx >> 10;
        int rem = idx & 1023;
        int row = rem >> 3, c16 = rem & 7;
        int n = ntile * 128 + row;
        int iy = (n >> 6) + dy;
        int ix = (n & 63) + dx;
        bool ok = (iy >= 0) && (iy < H_) && (ix >= 0) && (ix < W_);
        size_t so = ((size_t)b * N_ + (size_t)(ok ? (iy * 64 + ix) : 0)) * C_ +
                    cic * 64 + c16 * 8;
        const char* src = (plane ? (const char*)g_xt_lo : (const char*)g_xt_hi) + so * 2;
        cpa16z(sb + GM_B_OFF + buf * 32768 + plane * 16384 + SWZ(row * 128 + c16 * 16),
               src, ok ? 16u : 0u);
    }
}

__global__ void __launch_bounds__(512, 1) gemm_qkv_kernel(
    const float* __restrict__ bq, const float* __restrict__ bk,
    const float* __restrict__ bv)
{
    extern __shared__ char smem[];
    uint32_t sb = smem_u32(smem);
    const int tid = threadIdx.x, L = tid & 31, w = tid >> 5;
    const int mw = w & 3, nw = w >> 2;
    const int cot = blockIdx.x, ntile = blockIdx.y, b = blockIdx.z;
    const int co0 = cot * 128;

    uint32_t RAm[2], sAm[2];
#pragma unroll
    for (int m = 0; m < 2; m++) {
        uint32_t row = (uint32_t)(mw * 32 + m * 16 + (L & 15));
        RAm[m] = row * 128;
        sAm[m] = (row & 7) << 4;
    }
    const uint32_t colA = (L & 16) ? 16u : 0u;
    uint32_t RB[2], sB[2];
#pragma unroll
    for (int j = 0; j < 2; j++) {
        uint32_t row = (uint32_t)((nw * 4 + j * 2 + (L >> 4)) * 8 + (L & 7));
        RB[j] = row * 128;
        sB[j] = (row & 7) << 4;
    }
    const uint32_t colB = (uint32_t)(L & 8) * 2;

    float d[8][4];
#pragma unroll
    for (int f = 0; f < 8; f++)
#pragma unroll
        for (int i = 0; i < 4; i++) d[f][i] = 0.f;

    gemm_stage(sb, co0, b, ntile, 0, 0, tid);
    CP_COMMIT();
    gemm_stage(sb, co0, b, ntile, 1, 1, tid);
    CP_COMMIT();

#pragma unroll 1
    for (int kc = 0; kc < NKCH; kc++) {
        const int buf = kc % 3;
        if (kc == NKCH - 1) { CP_WAIT(0); } else { CP_WAIT(1); }
        __syncthreads();
        if (kc < NKCH - 2) {
            gemm_stage(sb, co0, b, ntile, kc + 2, (kc + 2) % 3, tid);
            CP_COMMIT();
        }

        const uint32_t Ab = sb + buf * 32768;
        const uint32_t Bb = sb + GM_B_OFF + buf * 32768;
#pragma unroll
        for (int pass = 0; pass < 3; pass++) {
            const uint32_t Ap = Ab + ((pass == 2) ? 16384u : 0u);
            const uint32_t Bp = Bb + ((pass == 1) ? 16384u : 0u);
#pragma unroll
            for (int kk = 0; kk < 4; kk++) {
                const uint32_t kca = (uint32_t)(kk * 32) + colA;
                const uint32_t kcb = (uint32_t)(kk * 32) + colB;
                uint32_t a0[4], a1[4];
                ldm_x4(Ap + RAm[0] + (kca ^ sAm[0]), a0);
                ldm_x4(Ap + RAm[1] + (kca ^ sAm[1]), a1);
#pragma unroll
                for (int j = 0; j < 2; j++) {
                    uint32_t bb[4];
                    ldm_x4(Bp + RB[j] + (kcb ^ sB[j]), bb);
                    mma_bf16(d[2 * j],         a0, bb);
                    mma_bf16(d[2 * j + 1],     a0, bb + 2);
                    mma_bf16(d[4 + 2 * j],     a1, bb);
                    mma_bf16(d[4 + 2 * j + 1], a1, bb + 2);
                }
            }
        }
    }

    // ---- epilogue
    __syncthreads();
    float* sD = (float*)smem;
#pragma unroll
    for (int m = 0; m < 2; m++)
#pragma unroll
        for (int jn = 0; jn < 4; jn++) {
            int f = m * 4 + jn;
            int r0 = mw * 32 + m * 16 + (L >> 2);
            int n0 = nw * 32 + jn * 8 + 2 * (L & 3);
            sD[r0 * 130 + n0]           = d[f][0];
            sD[r0 * 130 + n0 + 1]       = d[f][1];
            sD[(r0 + 8) * 130 + n0]     = d[f][2];
            sD[(r0 + 8) * 130 + n0 + 1] = d[f][3];
        }
    __syncthreads();

    const size_t bn0 = (size_t)b * N_ + (size_t)ntile * 128;
    if (cot == 0) {
        // rows 0-63 -> q fp16 [b][n][64], rows 64-127 -> k fp16
#pragma unroll 1
        for (int i = 0; i < 8; i++) {
            int idx = tid + i * 512;        // 4096 = 128 n x 32 co-pairs
            int n = idx >> 5, cp = idx & 31;
            size_t off = ((bn0 + n) * HID_ + 2 * cp) * 2;
            {
                float v0 = sD[(2 * cp) * 130 + n]     + bq[2 * cp];
                float v1 = sD[(2 * cp + 1) * 130 + n] + bq[2 * cp + 1];
                __half2 hh = __floats2half2_rn(v0, v1);
                *(uint32_t*)((char*)g_q_h + off) = *(uint32_t*)&hh;
            }
            {
                float v0 = sD[(64 + 2 * cp) * 130 + n]     + bk[2 * cp];
                float v1 = sD[(64 + 2 * cp + 1) * 130 + n] + bk[2 * cp + 1];
                __half2 hh = __floats2half2_rn(v0, v1);
                *(uint32_t*)((char*)g_k_h + off) = *(uint32_t*)&hh;
            }
        }
    } else {
        const int cv0 = (cot - 1) * 128;
        const size_t n0g = (size_t)ntile * 128;
#pragma unroll 1
        for (int i = 0; i < 16; i++) {
            int idx = tid + i * 512;
            int co = idx >> 6, np = idx & 63;
            float bb = bv[cv0 + co];
            float v0 = sD[co * 130 + 2 * np]     + bb;
            float v1 = sD[co * 130 + 2 * np + 1] + bb;
            __half2 hh = __floats2half2_rn(v0, v1);
            size_t off = (((size_t)b * C_ + cv0 + co) * N_ + n0g + 2 * np) * 2;
            *(uint32_t*)((char*)g_v_h + off) = *(uint32_t*)&hh;
        }
    }
}

// ---------------------------------------------------------------------------
// Flash attention: S fp16 single-pass, ONLINE softmax, P+V fp16 single-plane.
// ---------------------------------------------------------------------------
#define SM_Q    0                     // 16384 (128 q x 128B)
#define SM_P    16384                 // 16384
#define SM_RS   32768                 // 1024
#define SM_MX   33792                 // 1024
#define SM_K    34816                 // + buf*8192  (2 x 8KB)
#define SM_V    51200                 // + buf*32768 (2 x 32KB)
#define SM_TOT  182272                // SM_V + 131072 (epilogue staging)

__device__ __forceinline__ void load_qtile(uint32_t sb, int b, int m0, int tid) {
    const char* qh = (const char*)g_q_h + ((size_t)b * N_ + m0) * HID_ * 2;
#pragma unroll
    for (int i = 0; i < 2; i++) {
        int idx = tid + i * 512;              // 1024 chunks of 16B
        int row = idx >> 3, c = (idx & 7) * 16;
        cpa16(sb + SM_Q + SWZ(row * 128 + c), qh + row * 128 + c);
    }
}

__device__ __forceinline__ void load_kv(uint32_t sb, int b, int nt, int tid) {
    const int buf = nt & 1;
    const char* kh = (const char*)g_k_h + ((size_t)b * N_ + (size_t)nt * 64) * HID_ * 2;
    {
        int row = tid >> 3, c = (tid & 7) * 16;   // 512 chunks = 8KB
        cpa16(sb + SM_K + buf * 8192 + SWZ(row * 128 + c), kh + row * 128 + c);
    }
    const char* vh = (const char*)g_v_h + ((size_t)b * C_ * N_ + (size_t)nt * 64) * 2;
#pragma unroll
    for (int i = 0; i < 4; i++) {
        int idx = tid + i * 512;              // 2048 chunks = 32KB
        int row = idx >> 3, c = (idx & 7) * 16;
        cpa16(sb + SM_V + buf * 32768 + SWZ(row * 128 + c),
              vh + (size_t)row * (N_ * 2) + c);
    }
}

__global__ void __launch_bounds__(512, 1) flash_mma_kernel(
    const float* __restrict__ x, float* __restrict__ out)
{
    extern __shared__ char smem[];
    uint32_t sb = smem_u32(smem);
    const int tid = threadIdx.x;
    const int L   = tid & 31;
    const int w   = tid >> 5;
    const int rb  = w & 7;
    const int ch  = w >> 3;
    const int b   = blockIdx.y;
    const int m0  = blockIdx.x * 128;

    load_qtile(sb, b, m0, tid);
    load_kv(sb, b, 0, tid);
    CP_COMMIT();
    load_kv(sb, b, 1, tid);
    CP_COMMIT();

    const uint32_t RA   = (uint32_t)(rb * 16 + (L & 15)) * 128;
    const uint32_t sA   = (RA >> 3) & 0x70;
    const uint32_t colA = (L & 16) ? 16u : 0u;
    uint32_t RBs[2], sBs[2];
#pragma unroll
    for (int nnb = 0; nnb < 2; nnb++) {
        uint32_t row = (uint32_t)((ch * 4 + nnb * 2 + (L >> 4)) * 8 + (L & 7));
        RBs[nnb] = row * 128;
        sBs[nnb] = (RBs[nnb] >> 3) & 0x70;
    }
    const uint32_t colB = (uint32_t)(L & 8) * 2;
    const uint32_t colV = (uint32_t)((L & 8) * 2 + (L & 16) * 2);
    const uint32_t RP0  = (uint32_t)(rb * 16 + (L >> 2)) * 128;
    const uint32_t sP0  = (RP0 >> 3) & 0x70;
    const uint32_t RP1  = RP0 + 8 * 128;
    const uint32_t sP1  = (RP1 >> 3) & 0x70;
    const int rown = rb * 16 + (L >> 2);
    float* sRS = (float*)(smem + SM_RS);
    float* sMX = (float*)(smem + SM_MX);

    float O[16][4];
#pragma unroll
    for (int cc = 0; cc < 16; cc++)
#pragma unroll
        for (int i = 0; i < 4; i++) O[cc][i] = 0.f;
    float l0 = 0.f, l1 = 0.f;
    float mr0 = -INFINITY, mr1 = -INFINITY;

    for (int nt = 0; nt < 64; nt++) {
        const int buf = nt & 1;
        if (nt == 63) { CP_WAIT(0); } else { CP_WAIT(1); }
        __syncthreads();

        // ---- S = Q K^T (fp16 single pass, fp32 accum)
        float d[4][4];
#pragma unroll
        for (int nn = 0; nn < 4; nn++)
#pragma unroll
            for (int i = 0; i < 4; i++) d[nn][i] = 0.f;

        const uint32_t kb0 = sb + SM_K + buf * 8192;
#pragma unroll
        for (int kk = 0; kk < 4; kk++) {
            uint32_t a[4];
            ldm_x4(sb + SM_Q + RA + ((kk * 32 + colA) ^ sA), a);
#pragma unroll
            for (int nnb = 0; nnb < 2; nnb++) {
                uint32_t bb[4];
                ldm_x4(kb0 + RBs[nnb] + (((uint32_t)(kk * 32) + colB) ^ sBs[nnb]), bb);
                mma_f16(d[nnb * 2],     a, bb);
                mma_f16(d[nnb * 2 + 1], a, bb + 2);
            }
        }

        // ---- online row max (4-lane shfl + cross-warp exchange)
        float mx0 = fmaxf(fmaxf(d[0][0], d[0][1]), fmaxf(d[1][0], d[1][1]));
        mx0 = fmaxf(mx0, fmaxf(fmaxf(d[2][0], d[2][1]), fmaxf(d[3][0], d[3][1])));
        float mx1 = fmaxf(fmaxf(d[0][2], d[0][3]), fmaxf(d[1][2], d[1][3]));
        mx1 = fmaxf(mx1, fmaxf(fmaxf(d[2][2], d[2][3]), fmaxf(d[3][2], d[3][3])));
        mx0 = fmaxf(mx0, __shfl_xor_sync(~0u, mx0, 1));
        mx0 = fmaxf(mx0, __shfl_xor_sync(~0u, mx0, 2));
        mx1 = fmaxf(mx1, __shfl_xor_sync(~0u, mx1, 1));
        mx1 = fmaxf(mx1, __shfl_xor_sync(~0u, mx1, 2));
        if ((L & 3) == 0) {
            sMX[ch * 128 + rown]     = mx0;
            sMX[ch * 128 + rown + 8] = mx1;
        }
        __syncthreads();
        mx0 = fmaxf(mx0, sMX[(ch ^ 1) * 128 + rown]);
        mx1 = fmaxf(mx1, sMX[(ch ^ 1) * 128 + rown + 8]);
        const float mn0 = fmaxf(mr0, mx0), mn1 = fmaxf(mr1, mx1);
        const float a0 = __expf(mr0 - mn0), a1 = __expf(mr1 - mn1);
        mr0 = mn0; mr1 = mn1;

        // ---- p = exp(s - rowmax) -> fp16; l accumulates the ROUNDED p
        float ps0 = 0.f, ps1 = 0.f;
#pragma unroll
        for (int nn = 0; nn < 4; nn++) {
            float e00 = __expf(d[nn][0] - mn0), e01 = __expf(d[nn][1] - mn0);
            float e10 = __expf(d[nn][2] - mn1), e11 = __expf(d[nn][3] - mn1);
            __half2 p0 = __floats2half2_rn(e00, e01);
            __half2 p1 = __floats2half2_rn(e10, e11);
            float2 f0 = __half22float2(p0);
            float2 f1 = __half22float2(p1);
            ps0 += f0.x + f0.y; ps1 += f1.x + f1.y;
            uint32_t cbyte = (uint32_t)((ch * 32 + nn * 8 + 2 * (L & 3)) * 2);
            *(uint32_t*)(smem + SM_P + RP0 + (cbyte ^ sP0)) = *(uint32_t*)&p0;
            *(uint32_t*)(smem + SM_P + RP1 + (cbyte ^ sP1)) = *(uint32_t*)&p1;
        }
        ps0 += __shfl_xor_sync(~0u, ps0, 1);
        ps0 += __shfl_xor_sync(~0u, ps0, 2);
        ps1 += __shfl_xor_sync(~0u, ps1, 1);
        ps1 += __shfl_xor_sync(~0u, ps1, 2);
        if ((L & 3) == 0) {
            sRS[ch * 128 + rown]     = ps0;
            sRS[ch * 128 + rown + 8] = ps1;
        }
        __syncthreads();
        l0 = l0 * a0 + ps0 + sRS[(ch ^ 1) * 128 + rown];
        l1 = l1 * a1 + ps1 + sRS[(ch ^ 1) * 128 + rown + 8];

        // ---- rescale O, then O += P * V (fp16)
#pragma unroll
        for (int cc = 0; cc < 16; cc++) {
            O[cc][0] *= a0; O[cc][1] *= a0; O[cc][2] *= a1; O[cc][3] *= a1;
        }

        uint32_t pa[4][4];
#pragma unroll
        for (int kk = 0; kk < 4; kk++)
            ldm_x4(sb + SM_P + RA + ((kk * 32 + colA) ^ sA), pa[kk]);

        const uint32_t vb0 = sb + SM_V + buf * 32768;
#pragma unroll
        for (int cc = 0; cc < 16; cc++) {
            uint32_t row = (uint32_t)(ch * 128 + cc * 8 + (L & 7));
            uint32_t RB = row * 128, sB = (row & 7) << 4;
            uint32_t vb = vb0 + RB;
            uint32_t b01[4], b23[4];
            ldm_x4(vb + (colV ^ sB), b01);
            ldm_x4(vb + ((64 + colV) ^ sB), b23);
            mma_f16(O[cc], pa[0], b01); mma_f16(O[cc], pa[1], b01 + 2);
            mma_f16(O[cc], pa[2], b23); mma_f16(O[cc], pa[3], b23 + 2);
        }
        __syncthreads();
        if (nt < 62) { load_kv(sb, b, nt + 2, tid); CP_COMMIT(); }
    }

    const float inv0 = 1.f / l0, inv1 = 1.f / l1;
    float* sO = (float*)(smem + SM_V + ch * 65536);
    const int gg = rb * 16 + (L >> 2), tt = L & 3;
#pragma unroll
    for (int cc = 0; cc < 16; cc++) {
        int c0 = cc * 8 + 2 * tt;
        sO[c0 * 128 + gg]           = O[cc][0] * inv0;
        sO[(c0 + 1) * 128 + gg]     = O[cc][1] * inv0;
        sO[c0 * 128 + gg + 8]       = O[cc][2] * inv1;
        sO[(c0 + 1) * 128 + gg + 8] = O[cc][3] * inv1;
    }
    __syncthreads();

    const float* xb = x   + (size_t)b * C_ * N_ + m0;
    float*       ob = out + (size_t)b * C_ * N_ + m0;
#pragma unroll 1
    for (int i = 0; i < 16; i++) {
        int idx = tid + i * 512;
        int c = idx >> 5, m4 = (idx & 31) * 4;
        float4 vo = *(float4*)(smem + SM_V + (size_t)(c >> 7) * 65536 +
                               (size_t)(c & 127) * 512 + (size_t)m4 * 4);
        float4 vx = *(const float4*)(xb + (size_t)c * N_ + m4);
        vo.x += vx.x; vo.y += vx.y; vo.z += vx.z; vo.w += vx.w;
        *(float4*)(ob + (size_t)c * N_ + m4) = vo;
    }
}

// ---------------------------------------------------------------------------
extern "C" void kernel_launch(void* const* d_in, const int* in_sizes, int n_in,
                              void* d_out, int out_size)
{
    const float* x  = (const float*)d_in[0];
    const float* Wq = (const float*)d_in[1];
    const float* bq = (const float*)d_in[2];
    const float* Wk = (const float*)d_in[3];
    const float* bk = (const float*)d_in[4];
    const float* Wv = (const float*)d_in[5];
    const float* bv = (const float*)d_in[6];
    float* out = (float*)d_out;

    xsplit_kernel<<<dim3(64, 4, 8), 256>>>(x);
    wsplit_kernel<<<384, 256>>>(Wq, Wk, Wv);

    cudaFuncSetAttribute(gemm_qkv_kernel,
                         cudaFuncAttributeMaxDynamicSharedMemorySize, GM_TOT);
    gemm_qkv_kernel<<<dim3(3, 32, 8), 512, GM_TOT>>>(bq, bk, bv);

    cudaFuncSetAttribute(flash_mma_kernel,
                         cudaFuncAttributeMaxDynamicSharedMemorySize, SM_TOT);
    flash_mma_kernel<<<dim3(32, 8), 512, SM_TOT>>>(x, out);
}

// round 15
// speedup vs baseline: 1.4278x; 1.2414x over previous
#include <cuda_runtime.h>
#include <cuda_bf16.h>
#include <cuda_fp16.h>
#include <cstdint>
#include <math.h>

#define B_ 8
#define C_ 256
#define HID_ 64
#define H_ 64
#define W_ 64
#define N_ 4096
#define KTOT 2304          // 9 taps * 256 ci
#define NKCH 36            // KTOT / 64

// ---------------- device scratch ----------------
__device__ __align__(256) __half        g_q_h[(size_t)B_ * N_ * HID_];  // fp16 Q
__device__ __align__(256) __half        g_k_h[(size_t)B_ * N_ * HID_];  // fp16 K
__device__ __align__(256) __half        g_v_h[(size_t)B_ * C_ * N_];    // fp16 V
// x transposed: [b][n][ci]  (bf16 hi/lo for q/k conv, fp16 for v conv)
__device__ __align__(256) __nv_bfloat16 g_xt_hi[(size_t)B_ * N_ * C_];
__device__ __align__(256) __nv_bfloat16 g_xt_lo[(size_t)B_ * N_ * C_];
__device__ __align__(256) __half        g_xt_h[(size_t)B_ * N_ * C_];
// q/k weights bf16 hi/lo: [co 0..127][tap*256+ci]  (0-63 q, 64-127 k)
__device__ __align__(256) __nv_bfloat16 g_w_hi[128 * KTOT], g_w_lo[128 * KTOT];
// v weights fp16: [co 0..255][tap*256+ci]
__device__ __align__(256) __half        g_wv_h[256 * KTOT];

// ---------------- PTX helpers (sm_80-compatible only) ----------------
__device__ __forceinline__ uint32_t smem_u32(const void* p) {
    uint32_t a;
    asm("{ .reg .u64 t; cvta.to.shared.u64 t, %1; cvt.u32.u64 %0, t; }" : "=r"(a) : "l"(p));
    return a;
}
#define SWZ(x) ((uint32_t)(x) ^ ((((uint32_t)(x)) >> 3) & 0x70u))

__device__ __forceinline__ void cpa16(uint32_t dst, const void* src) {
    asm volatile("cp.async.cg.shared.global [%0], [%1], 16;" :: "r"(dst), "l"(src));
}
__device__ __forceinline__ void cpa16z(uint32_t dst, const void* src, uint32_t sz) {
    asm volatile("cp.async.cg.shared.global [%0], [%1], 16, %2;"
                 :: "r"(dst), "l"(src), "r"(sz));
}
#define CP_COMMIT() asm volatile("cp.async.commit_group;")
#define CP_WAIT(n)  asm volatile("cp.async.wait_group %0;" :: "n"(n))

__device__ __forceinline__ void ldm_x4(uint32_t a, uint32_t* r) {
    asm volatile("ldmatrix.sync.aligned.m8n8.x4.shared.b16 {%0,%1,%2,%3}, [%4];"
        : "=r"(r[0]), "=r"(r[1]), "=r"(r[2]), "=r"(r[3]) : "r"(a));
}
__device__ __forceinline__ void mma_bf16(float* d, const uint32_t* a, const uint32_t* b) {
    asm volatile("mma.sync.aligned.m16n8k16.row.col.f32.bf16.bf16.f32 "
        "{%0,%1,%2,%3}, {%4,%5,%6,%7}, {%8,%9}, {%0,%1,%2,%3};"
        : "+f"(d[0]), "+f"(d[1]), "+f"(d[2]), "+f"(d[3])
        : "r"(a[0]), "r"(a[1]), "r"(a[2]), "r"(a[3]), "r"(b[0]), "r"(b[1]));
}
__device__ __forceinline__ void mma_f16(float* d, const uint32_t* a, const uint32_t* b) {
    asm volatile("mma.sync.aligned.m16n8k16.row.col.f32.f16.f16.f32 "
        "{%0,%1,%2,%3}, {%4,%5,%6,%7}, {%8,%9}, {%0,%1,%2,%3};"
        : "+f"(d[0]), "+f"(d[1]), "+f"(d[2]), "+f"(d[3])
        : "r"(a[0]), "r"(a[1]), "r"(a[2]), "r"(a[3]), "r"(b[0]), "r"(b[1]));
}
__device__ __forceinline__ uint32_t pack_bf2(float a, float b) {
    __nv_bfloat162 t = __floats2bfloat162_rn(a, b);
    return *(uint32_t*)&t;
}

// ---------------------------------------------------------------------------
// Prep 1: x [b][ci][n] fp32 -> xt bf16 hi/lo + fp16 planes. grid(64,4,8), 256 thr
// ---------------------------------------------------------------------------
__global__ __launch_bounds__(256) void xsplit_kernel(const float* __restrict__ x)
{
    __shared__ float st[64][65];
    const int b = blockIdx.z, ci0 = blockIdx.y * 64, n0 = blockIdx.x * 64;
    const int tid = threadIdx.x, L = tid & 31, w = tid >> 5;
#pragma unroll
    for (int i = 0; i < 4; i++) {
        int j = i * 256 + tid;
        int ci = j >> 4, c4 = (j & 15) * 4;
        float4 v = *(const float4*)(x + ((size_t)b * C_ + ci0 + ci) * N_ + n0 + c4);
        st[ci][c4] = v.x; st[ci][c4 + 1] = v.y; st[ci][c4 + 2] = v.z; st[ci][c4 + 3] = v.w;
    }
    __syncthreads();
#pragma unroll
    for (int i = 0; i < 8; i++) {
        int n = w * 8 + i;
        float v0 = st[2 * L][n], v1 = st[2 * L + 1][n];
        __nv_bfloat16 h0 = __float2bfloat16(v0), h1 = __float2bfloat16(v1);
        float l0 = v0 - __bfloat162float(h0), l1 = v1 - __bfloat162float(h1);
        size_t gb = ((size_t)b * N_ + n0 + n) * C_ + ci0;
        __nv_bfloat162 hh; hh.x = h0; hh.y = h1;
        *(uint32_t*)((char*)g_xt_hi + gb * 2 + L * 4) = *(uint32_t*)&hh;
        *(uint32_t*)((char*)g_xt_lo + gb * 2 + L * 4) = pack_bf2(l0, l1);
        __half2 fh = __floats2half2_rn(v0, v1);
        *(uint32_t*)((char*)g_xt_h + gb * 2 + L * 4) = *(uint32_t*)&fh;
    }
}

// ---------------------------------------------------------------------------
// Prep 2: weights: q/k -> bf16 hi/lo [co<128]; v -> fp16 [co 0..255]
// grid(384), 256 thr
// ---------------------------------------------------------------------------
__global__ __launch_bounds__(256) void wsplit_kernel(
    const float* __restrict__ Wq, const float* __restrict__ Wk,
    const float* __restrict__ Wv)
{
    int t = blockIdx.x * 256 + threadIdx.x;   // 0..98303
    int co = t >> 8, ci = t & 255;
    if (co < 128) {
        const float* src = (co < 64) ? Wq : Wk;
        int lc = co & 63;
#pragma unroll
        for (int kk = 0; kk < 9; kk++) {
            float v = src[((size_t)lc * 256 + ci) * 9 + kk];
            __nv_bfloat16 h = __float2bfloat16(v);
            size_t o = (size_t)co * KTOT + kk * 256 + ci;
            g_w_hi[o] = h;
            g_w_lo[o] = __float2bfloat16(v - __bfloat162float(h));
        }
    } else {
        int lc = co - 128;
#pragma unroll
        for (int kk = 0; kk < 9; kk++) {
            float v = Wv[((size_t)lc * 256 + ci) * 9 + kk];
            g_wv_h[(size_t)lc * KTOT + kk * 256 + ci] = __float2half(v);
        }
    }
}

// ---------------------------------------------------------------------------
// QKV GEMM, implicit im2col. cot==0: q/k bf16 hi/lo 3-pass (2 planes).
// cot 1,2: v fp16 single-pass (1 plane). Triple-buffered, 1 barrier per kc.
// ---------------------------------------------------------------------------
#define GM_B_OFF 98304
#define GM_TOT   196608

__device__ __forceinline__ void gemm_stage_qk(uint32_t sb, int b, int ntile,
                                              int kc, int buf, int tid) {
    const int tap = kc >> 2, cic = kc & 3;
    const int dy = tap / 3 - 1, dx = tap % 3 - 1;
#pragma unroll
    for (int i = 0; i < 4; i++) {       // A: weights [128 co][64 k], 2 planes
        int idx = tid + i * 512;
        int plane = idx >> 10;
        int rem = idx & 1023;
        int row = rem >> 3, c16 = rem & 7;
        const char* src = (plane ? (const char*)g_w_lo : (const char*)g_w_hi) +
                          ((size_t)row * KTOT + kc * 64 + c16 * 8) * 2;
        cpa16(sb + buf * 32768 + plane * 16384 + SWZ(row * 128 + c16 * 16), src);
    }
#pragma unroll
    for (int i = 0; i < 4; i++) {       // B: shifted xt rows, 2 planes
        int idx = tid + i * 512;
        int plane = idx >> 10;
        int rem = idx & 1023;
        int row = rem >> 3, c16 = rem & 7;
        int n = ntile * 128 + row;
        int iy = (n >> 6) + dy;
        int ix = (n & 63) + dx;
        bool ok = (iy >= 0) && (iy < H_) && (ix >= 0) && (ix < W_);
        size_t so = ((size_t)b * N_ + (size_t)(ok ? (iy * 64 + ix) : 0)) * C_ +
                    cic * 64 + c16 * 8;
        const char* src = (plane ? (const char*)g_xt_lo : (const char*)g_xt_hi) + so * 2;
        cpa16z(sb + GM_B_OFF + buf * 32768 + plane * 16384 + SWZ(row * 128 + c16 * 16),
               src, ok ? 16u : 0u);
    }
}

__device__ __forceinline__ void gemm_stage_v(uint32_t sb, int co0v, int b, int ntile,
                                             int kc, int buf, int tid) {
    const int tap = kc >> 2, cic = kc & 3;
    const int dy = tap / 3 - 1, dx = tap % 3 - 1;
#pragma unroll
    for (int i = 0; i < 2; i++) {       // A: v-weights fp16 [128 co][64 k]
        int idx = tid + i * 512;        // 0..1023
        int row = idx >> 3, c16 = idx & 7;
        const char* src = (const char*)g_wv_h +
                          (((size_t)(co0v + row)) * KTOT + kc * 64 + c16 * 8) * 2;
        cpa16(sb + buf * 32768 + SWZ(row * 128 + c16 * 16), src);
    }
#pragma unroll
    for (int i = 0; i < 2; i++) {       // B: shifted fp16 xt rows
        int idx = tid + i * 512;
        int row = idx >> 3, c16 = idx & 7;
        int n = ntile * 128 + row;
        int iy = (n >> 6) + dy;
        int ix = (n & 63) + dx;
        bool ok = (iy >= 0) && (iy < H_) && (ix >= 0) && (ix < W_);
        size_t so = ((size_t)b * N_ + (size_t)(ok ? (iy * 64 + ix) : 0)) * C_ +
                    cic * 64 + c16 * 8;
        cpa16z(sb + GM_B_OFF + buf * 32768 + SWZ(row * 128 + c16 * 16),
               (const char*)g_xt_h + so * 2, ok ? 16u : 0u);
    }
}

__global__ void __launch_bounds__(512, 1) gemm_qkv_kernel(
    const float* __restrict__ bq, const float* __restrict__ bk,
    const float* __restrict__ bv)
{
    extern __shared__ char smem[];
    uint32_t sb = smem_u32(smem);
    const int tid = threadIdx.x, L = tid & 31, w = tid >> 5;
    const int mw = w & 3, nw = w >> 2;
    const int cot = blockIdx.x, ntile = blockIdx.y, b = blockIdx.z;
    const bool isQK = (cot == 0);
    const int co0v = isQK ? 0 : (cot - 1) * 128;

    uint32_t RAm[2], sAm[2];
#pragma unroll
    for (int m = 0; m < 2; m++) {
        uint32_t row = (uint32_t)(mw * 32 + m * 16 + (L & 15));
        RAm[m] = row * 128;
        sAm[m] = (row & 7) << 4;
    }
    const uint32_t colA = (L & 16) ? 16u : 0u;
    uint32_t RB[2], sB[2];
#pragma unroll
    for (int j = 0; j < 2; j++) {
        uint32_t row = (uint32_t)((nw * 4 + j * 2 + (L >> 4)) * 8 + (L & 7));
        RB[j] = row * 128;
        sB[j] = (row & 7) << 4;
    }
    const uint32_t colB = (uint32_t)(L & 8) * 2;

    float d[8][4];
#pragma unroll
    for (int f = 0; f < 8; f++)
#pragma unroll
        for (int i = 0; i < 4; i++) d[f][i] = 0.f;

    if (isQK) {
        gemm_stage_qk(sb, b, ntile, 0, 0, tid);
        CP_COMMIT();
        gemm_stage_qk(sb, b, ntile, 1, 1, tid);
        CP_COMMIT();
    } else {
        gemm_stage_v(sb, co0v, b, ntile, 0, 0, tid);
        CP_COMMIT();
        gemm_stage_v(sb, co0v, b, ntile, 1, 1, tid);
        CP_COMMIT();
    }

#pragma unroll 1
    for (int kc = 0; kc < NKCH; kc++) {
        const int buf = kc % 3;
        if (kc == NKCH - 1) { CP_WAIT(0); } else { CP_WAIT(1); }
        __syncthreads();
        if (kc < NKCH - 2) {
            if (isQK) gemm_stage_qk(sb, b, ntile, kc + 2, (kc + 2) % 3, tid);
            else      gemm_stage_v(sb, co0v, b, ntile, kc + 2, (kc + 2) % 3, tid);
            CP_COMMIT();
        }

        const uint32_t Ab = sb + buf * 32768;
        const uint32_t Bb = sb + GM_B_OFF + buf * 32768;
        if (isQK) {
#pragma unroll
            for (int pass = 0; pass < 3; pass++) {
                const uint32_t Ap = Ab + ((pass == 2) ? 16384u : 0u);
                const uint32_t Bp = Bb + ((pass == 1) ? 16384u : 0u);
#pragma unroll
                for (int kk = 0; kk < 4; kk++) {
                    const uint32_t kca = (uint32_t)(kk * 32) + colA;
                    const uint32_t kcb = (uint32_t)(kk * 32) + colB;
                    uint32_t a0[4], a1[4];
                    ldm_x4(Ap + RAm[0] + (kca ^ sAm[0]), a0);
                    ldm_x4(Ap + RAm[1] + (kca ^ sAm[1]), a1);
#pragma unroll
                    for (int j = 0; j < 2; j++) {
                        uint32_t bb[4];
                        ldm_x4(Bp + RB[j] + (kcb ^ sB[j]), bb);
                        mma_bf16(d[2 * j],         a0, bb);
                        mma_bf16(d[2 * j + 1],     a0, bb + 2);
                        mma_bf16(d[4 + 2 * j],     a1, bb);
                        mma_bf16(d[4 + 2 * j + 1], a1, bb + 2);
                    }
                }
            }
        } else {
#pragma unroll
            for (int kk = 0; kk < 4; kk++) {
                const uint32_t kca = (uint32_t)(kk * 32) + colA;
                const uint32_t kcb = (uint32_t)(kk * 32) + colB;
                uint32_t a0[4], a1[4];
                ldm_x4(Ab + RAm[0] + (kca ^ sAm[0]), a0);
                ldm_x4(Ab + RAm[1] + (kca ^ sAm[1]), a1);
#pragma unroll
                for (int j = 0; j < 2; j++) {
                    uint32_t bb[4];
                    ldm_x4(Bb + RB[j] + (kcb ^ sB[j]), bb);
                    mma_f16(d[2 * j],         a0, bb);
                    mma_f16(d[2 * j + 1],     a0, bb + 2);
                    mma_f16(d[4 + 2 * j],     a1, bb);
                    mma_f16(d[4 + 2 * j + 1], a1, bb + 2);
                }
            }
        }
    }

    // ---- epilogue
    __syncthreads();
    float* sD = (float*)smem;
#pragma unroll
    for (int m = 0; m < 2; m++)
#pragma unroll
        for (int jn = 0; jn < 4; jn++) {
            int f = m * 4 + jn;
            int r0 = mw * 32 + m * 16 + (L >> 2);
            int n0 = nw * 32 + jn * 8 + 2 * (L & 3);
            sD[r0 * 130 + n0]           = d[f][0];
            sD[r0 * 130 + n0 + 1]       = d[f][1];
            sD[(r0 + 8) * 130 + n0]     = d[f][2];
            sD[(r0 + 8) * 130 + n0 + 1] = d[f][3];
        }
    __syncthreads();

    const size_t bn0 = (size_t)b * N_ + (size_t)ntile * 128;
    if (isQK) {
        // rows 0-63 -> q fp16 [b][n][64], rows 64-127 -> k fp16
#pragma unroll 1
        for (int i = 0; i < 8; i++) {
            int idx = tid + i * 512;        // 4096 = 128 n x 32 co-pairs
            int n = idx >> 5, cp = idx & 31;
            size_t off = ((bn0 + n) * HID_ + 2 * cp) * 2;
            {
                float v0 = sD[(2 * cp) * 130 + n]     + bq[2 * cp];
                float v1 = sD[(2 * cp + 1) * 130 + n] + bq[2 * cp + 1];
                __half2 hh = __floats2half2_rn(v0, v1);
                *(uint32_t*)((char*)g_q_h + off) = *(uint32_t*)&hh;
            }
            {
                float v0 = sD[(64 + 2 * cp) * 130 + n]     + bk[2 * cp];
                float v1 = sD[(64 + 2 * cp + 1) * 130 + n] + bk[2 * cp + 1];
                __half2 hh = __floats2half2_rn(v0, v1);
                *(uint32_t*)((char*)g_k_h + off) = *(uint32_t*)&hh;
            }
        }
    } else {
        const size_t n0g = (size_t)ntile * 128;
#pragma unroll 1
        for (int i = 0; i < 16; i++) {
            int idx = tid + i * 512;
            int co = idx >> 6, np = idx & 63;
            float bb = bv[co0v + co];
            float v0 = sD[co * 130 + 2 * np]     + bb;
            float v1 = sD[co * 130 + 2 * np + 1] + bb;
            __half2 hh = __floats2half2_rn(v0, v1);
            size_t off = (((size_t)b * C_ + co0v + co) * N_ + n0g + 2 * np) * 2;
            *(uint32_t*)((char*)g_v_h + off) = *(uint32_t*)&hh;
        }
    }
}

// ---------------------------------------------------------------------------
// Flash attention (R14-proven, unchanged): S fp16, online softmax, P+V fp16.
// ---------------------------------------------------------------------------
#define SM_Q    0
#define SM_P    16384
#define SM_RS   32768
#define SM_MX   33792
#define SM_K    34816
#define SM_V    51200
#define SM_TOT  182272

__device__ __forceinline__ void load_qtile(uint32_t sb, int b, int m0, int tid) {
    const char* qh = (const char*)g_q_h + ((size_t)b * N_ + m0) * HID_ * 2;
#pragma unroll
    for (int i = 0; i < 2; i++) {
        int idx = tid + i * 512;
        int row = idx >> 3, c = (idx & 7) * 16;
        cpa16(sb + SM_Q + SWZ(row * 128 + c), qh + row * 128 + c);
    }
}

__device__ __forceinline__ void load_kv(uint32_t sb, int b, int nt, int tid) {
    const int buf = nt & 1;
    const char* kh = (const char*)g_k_h + ((size_t)b * N_ + (size_t)nt * 64) * HID_ * 2;
    {
        int row = tid >> 3, c = (tid & 7) * 16;
        cpa16(sb + SM_K + buf * 8192 + SWZ(row * 128 + c), kh + row * 128 + c);
    }
    const char* vh = (const char*)g_v_h + ((size_t)b * C_ * N_ + (size_t)nt * 64) * 2;
#pragma unroll
    for (int i = 0; i < 4; i++) {
        int idx = tid + i * 512;
        int row = idx >> 3, c = (idx & 7) * 16;
        cpa16(sb + SM_V + buf * 32768 + SWZ(row * 128 + c),
              vh + (size_t)row * (N_ * 2) + c);
    }
}

__global__ void __launch_bounds__(512, 1) flash_mma_kernel(
    const float* __restrict__ x, float* __restrict__ out)
{
    extern __shared__ char smem[];
    uint32_t sb = smem_u32(smem);
    const int tid = threadIdx.x;
    const int L   = tid & 31;
    const int w   = tid >> 5;
    const int rb  = w & 7;
    const int ch  = w >> 3;
    const int b   = blockIdx.y;
    const int m0  = blockIdx.x * 128;

    load_qtile(sb, b, m0, tid);
    load_kv(sb, b, 0, tid);
    CP_COMMIT();
    load_kv(sb, b, 1, tid);
    CP_COMMIT();

    const uint32_t RA   = (uint32_t)(rb * 16 + (L & 15)) * 128;
    const uint32_t sA   = (RA >> 3) & 0x70;
    const uint32_t colA = (L & 16) ? 16u : 0u;
    uint32_t RBs[2], sBs[2];
#pragma unroll
    for (int nnb = 0; nnb < 2; nnb++) {
        uint32_t row = (uint32_t)((ch * 4 + nnb * 2 + (L >> 4)) * 8 + (L & 7));
        RBs[nnb] = row * 128;
        sBs[nnb] = (RBs[nnb] >> 3) & 0x70;
    }
    const uint32_t colB = (uint32_t)(L & 8) * 2;
    const uint32_t colV = (uint32_t)((L & 8) * 2 + (L & 16) * 2);
    const uint32_t RP0  = (uint32_t)(rb * 16 + (L >> 2)) * 128;
    const uint32_t sP0  = (RP0 >> 3) & 0x70;
    const uint32_t RP1  = RP0 + 8 * 128;
    const uint32_t sP1  = (RP1 >> 3) & 0x70;
    const int rown = rb * 16 + (L >> 2);
    float* sRS = (float*)(smem + SM_RS);
    float* sMX = (float*)(smem + SM_MX);

    float O[16][4];
#pragma unroll
    for (int cc = 0; cc < 16; cc++)
#pragma unroll
        for (int i = 0; i < 4; i++) O[cc][i] = 0.f;
    float l0 = 0.f, l1 = 0.f;
    float mr0 = -INFINITY, mr1 = -INFINITY;

    for (int nt = 0; nt < 64; nt++) {
        const int buf = nt & 1;
        if (nt == 63) { CP_WAIT(0); } else { CP_WAIT(1); }
        __syncthreads();

        float d[4][4];
#pragma unroll
        for (int nn = 0; nn < 4; nn++)
#pragma unroll
            for (int i = 0; i < 4; i++) d[nn][i] = 0.f;

        const uint32_t kb0 = sb + SM_K + buf * 8192;
#pragma unroll
        for (int kk = 0; kk < 4; kk++) {
            uint32_t a[4];
            ldm_x4(sb + SM_Q + RA + ((kk * 32 + colA) ^ sA), a);
#pragma unroll
            for (int nnb = 0; nnb < 2; nnb++) {
                uint32_t bb[4];
                ldm_x4(kb0 + RBs[nnb] + (((uint32_t)(kk * 32) + colB) ^ sBs[nnb]), bb);
                mma_f16(d[nnb * 2],     a, bb);
                mma_f16(d[nnb * 2 + 1], a, bb + 2);
            }
        }

        float mx0 = fmaxf(fmaxf(d[0][0], d[0][1]), fmaxf(d[1][0], d[1][1]));
        mx0 = fmaxf(mx0, fmaxf(fmaxf(d[2][0], d[2][1]), fmaxf(d[3][0], d[3][1])));
        float mx1 = fmaxf(fmaxf(d[0][2], d[0][3]), fmaxf(d[1][2], d[1][3]));
        mx1 = fmaxf(mx1, fmaxf(fmaxf(d[2][2], d[2][3]), fmaxf(d[3][2], d[3][3])));
        mx0 = fmaxf(mx0, __shfl_xor_sync(~0u, mx0, 1));
        mx0 = fmaxf(mx0, __shfl_xor_sync(~0u, mx0, 2));
        mx1 = fmaxf(mx1, __shfl_xor_sync(~0u, mx1, 1));
        mx1 = fmaxf(mx1, __shfl_xor_sync(~0u, mx1, 2));
        if ((L & 3) == 0) {
            sMX[ch * 128 + rown]     = mx0;
            sMX[ch * 128 + rown + 8] = mx1;
        }
        __syncthreads();
        mx0 = fmaxf(mx0, sMX[(ch ^ 1) * 128 + rown]);
        mx1 = fmaxf(mx1, sMX[(ch ^ 1) * 128 + rown + 8]);
        const float mn0 = fmaxf(mr0, mx0), mn1 = fmaxf(mr1, mx1);
        const float a0 = __expf(mr0 - mn0), a1 = __expf(mr1 - mn1);
        mr0 = mn0; mr1 = mn1;

        float ps0 = 0.f, ps1 = 0.f;
#pragma unroll
        for (int nn = 0; nn < 4; nn++) {
            float e00 = __expf(d[nn][0] - mn0), e01 = __expf(d[nn][1] - mn0);
            float e10 = __expf(d[nn][2] - mn1), e11 = __expf(d[nn][3] - mn1);
            __half2 p0 = __floats2half2_rn(e00, e01);
            __half2 p1 = __floats2half2_rn(e10, e11);
            float2 f0 = __half22float2(p0);
            float2 f1 = __half22float2(p1);
            ps0 += f0.x + f0.y; ps1 += f1.x + f1.y;
            uint32_t cbyte = (uint32_t)((ch * 32 + nn * 8 + 2 * (L & 3)) * 2);
            *(uint32_t*)(smem + SM_P + RP0 + (cbyte ^ sP0)) = *(uint32_t*)&p0;
            *(uint32_t*)(smem + SM_P + RP1 + (cbyte ^ sP1)) = *(uint32_t*)&p1;
        }
        ps0 += __shfl_xor_sync(~0u, ps0, 1);
        ps0 += __shfl_xor_sync(~0u, ps0, 2);
        ps1 += __shfl_xor_sync(~0u, ps1, 1);
        ps1 += __shfl_xor_sync(~0u, ps1, 2);
        if ((L & 3) == 0) {
            sRS[ch * 128 + rown]     = ps0;
            sRS[ch * 128 + rown + 8] = ps1;
        }
        __syncthreads();
        l0 = l0 * a0 + ps0 + sRS[(ch ^ 1) * 128 + rown];
        l1 = l1 * a1 + ps1 + sRS[(ch ^ 1) * 128 + rown + 8];

#pragma unroll
        for (int cc = 0; cc < 16; cc++) {
            O[cc][0] *= a0; O[cc][1] *= a0; O[cc][2] *= a1; O[cc][3] *= a1;
        }

        uint32_t pa[4][4];
#pragma unroll
        for (int kk = 0; kk < 4; kk++)
            ldm_x4(sb + SM_P + RA + ((kk * 32 + colA) ^ sA), pa[kk]);

        const uint32_t vb0 = sb + SM_V + buf * 32768;
#pragma unroll
        for (int cc = 0; cc < 16; cc++) {
            uint32_t row = (uint32_t)(ch * 128 + cc * 8 + (L & 7));
            uint32_t RB = row * 128, sB = (row & 7) << 4;
            uint32_t vb = vb0 + RB;
            uint32_t b01[4], b23[4];
            ldm_x4(vb + (colV ^ sB), b01);
            ldm_x4(vb + ((64 + colV) ^ sB), b23);
            mma_f16(O[cc], pa[0], b01); mma_f16(O[cc], pa[1], b01 + 2);
            mma_f16(O[cc], pa[2], b23); mma_f16(O[cc], pa[3], b23 + 2);
        }
        __syncthreads();
        if (nt < 62) { load_kv(sb, b, nt + 2, tid); CP_COMMIT(); }
    }

    const float inv0 = 1.f / l0, inv1 = 1.f / l1;
    float* sO = (float*)(smem + SM_V + ch * 65536);
    const int gg = rb * 16 + (L >> 2), tt = L & 3;
#pragma unroll
    for (int cc = 0; cc < 16; cc++) {
        int c0 = cc * 8 + 2 * tt;
        sO[c0 * 128 + gg]           = O[cc][0] * inv0;
        sO[(c0 + 1) * 128 + gg]     = O[cc][1] * inv0;
        sO[c0 * 128 + gg + 8]       = O[cc][2] * inv1;
        sO[(c0 + 1) * 128 + gg + 8] = O[cc][3] * inv1;
    }
    __syncthreads();

    const float* xb = x   + (size_t)b * C_ * N_ + m0;
    float*       ob = out + (size_t)b * C_ * N_ + m0;
#pragma unroll 1
    for (int i = 0; i < 16; i++) {
        int idx = tid + i * 512;
        int c = idx >> 5, m4 = (idx & 31) * 4;
        float4 vo = *(float4*)(smem + SM_V + (size_t)(c >> 7) * 65536 +
                               (size_t)(c & 127) * 512 + (size_t)m4 * 4);
        float4 vx = *(const float4*)(xb + (size_t)c * N_ + m4);
        vo.x += vx.x; vo.y += vx.y; vo.z += vx.z; vo.w += vx.w;
        *(float4*)(ob + (size_t)c * N_ + m4) = vo;
    }
}

// ---------------------------------------------------------------------------
extern "C" void kernel_launch(void* const* d_in, const int* in_sizes, int n_in,
                              void* d_out, int out_size)
{
    const float* x  = (const float*)d_in[0];
    const float* Wq = (const float*)d_in[1];
    const float* bq = (const float*)d_in[2];
    const float* Wk = (const float*)d_in[3];
    const float* bk = (const float*)d_in[4];
    const float* Wv = (const float*)d_in[5];
    const float* bv = (const float*)d_in[6];
    float* out = (float*)d_out;

    xsplit_kernel<<<dim3(64, 4, 8), 256>>>(x);
    wsplit_kernel<<<384, 256>>>(Wq, Wk, Wv);

    cudaFuncSetAttribute(gemm_qkv_kernel,
                         cudaFuncAttributeMaxDynamicSharedMemorySize, GM_TOT);
    gemm_qkv_kernel<<<dim3(3, 32, 8), 512, GM_TOT>>>(bq, bk, bv);

    cudaFuncSetAttribute(flash_mma_kernel,
                         cudaFuncAttributeMaxDynamicSharedMemorySize, SM_TOT);
    flash_mma_kernel<<<dim3(32, 8), 512, SM_TOT>>>(x, out);
}